// round 4
// baseline (speedup 1.0000x reference)
#include <cuda_runtime.h>
#include <cstdint>

// Fixed problem: n=4, c=16, h=w=64, patch=3
#define NB 4
#define CH 16
#define HW 4096
#define KD 144
#define TM 128
#define TN 256
#define KC 16
#define JSPLIT 8
#define JRANGE (HW / JSPLIT)     // 512
#define JTILES (JRANGE / TN)     // 2
#define NCHUNK (KD / KC)         // 9
#define TCHUNK (JTILES * NCHUNK) // 18
#define SLOT_FLOATS (KC * 256 * 2)   // Q 4096 + P 4096
#define SMEM_BYTES (3 * SLOT_FLOATS * 4)  // 98304

// Scratch (__device__ globals: allocation-free)
__device__ float g_QdDup[(size_t)NB * KD * 2 * HW]; // [b][k][2*pix] dup pairs
__device__ float g_Pd[(size_t)NB * KD * HW];        // [b][k][pix]
__device__ float g_qn[NB * HW];
__device__ float g_pn[NB * HW];
__device__ float g_part_d[JSPLIT * NB * HW];
__device__ int   g_part_j[JSPLIT * NB * HW];

__device__ __forceinline__ unsigned long long ffma2(unsigned long long a,
                                                    unsigned long long b,
                                                    unsigned long long c) {
    asm("fma.rn.f32x2 %0, %1, %2, %0;" : "+l"(c) : "l"(a), "l"(b));
    return c;
}

#define CPA16(dst, src) \
    asm volatile("cp.async.cg.shared.global [%0], [%1], 16;\n" ::"r"(dst), "l"(src))

// ---------------------------------------------------------------------------
// Prep: patch descriptors (replicate-pad shifts) + squared norms.
// y==0: s -> duplicated Q layout; y==1: t -> plain P layout.
// ---------------------------------------------------------------------------
__global__ void prep_kernel(const float* __restrict__ s, const float* __restrict__ t) {
    int idx = blockIdx.x * blockDim.x + threadIdx.x;
    if (idx >= NB * HW) return;
    bool isP = blockIdx.y != 0;
    const float* src = isP ? t : s;

    int b = idx >> 12;
    int pix = idx & (HW - 1);
    int iy = pix >> 6, ix = pix & 63;

    float acc = 0.f;
    for (int c = 0; c < CH; c++) {
        const float* sc = src + ((size_t)(b * CH + c) << 12);
#pragma unroll
        for (int dy = 0; dy < 3; dy++) {
            int y = iy + dy - 1; y = y < 0 ? 0 : (y > 63 ? 63 : y);
#pragma unroll
            for (int dx = 0; dx < 3; dx++) {
                int x = ix + dx - 1; x = x < 0 ? 0 : (x > 63 ? 63 : x);
                float v = sc[(y << 6) + x];
                int kidx = c * 9 + dy * 3 + dx;
                if (isP) {
                    g_Pd[(size_t)(b * KD + kidx) * HW + pix] = v;
                } else {
                    float2 vv; vv.x = v; vv.y = v;
                    *reinterpret_cast<float2*>(
                        g_QdDup + (size_t)(b * KD + kidx) * 2 * HW + 2 * pix) = vv;
                }
                acc = fmaf(v, v, acc);
            }
        }
    }
    (isP ? g_pn : g_qn)[idx] = acc;
}

// ---------------------------------------------------------------------------
// Fused GEMM (FFMA2) + partial argmin.
// Grid (32, 8, 4) = (qtile, jsplit, batch). 512 threads.
// Warp grid 4x4: warp (wq, wt) owns 32q x 64t. Lane (lq, lt) owns 4q x 16t.
// Per-warp smem footprint per k: 256B (Q dup) + 256B (P) = 512B.
// ---------------------------------------------------------------------------
__global__ __launch_bounds__(512, 1) void nn_kernel() {
    extern __shared__ float sm[];

    const int b = blockIdx.z;
    const int js = blockIdx.y;
    const int q0 = blockIdx.x * TM;
    const int jbase = js * JRANGE;
    const int tid = threadIdx.x;
    const int wid = tid >> 5;
    const int lane = tid & 31;
    const int wq = wid >> 2, wt = wid & 3;
    const int lq = lane >> 2, lt = lane & 3;
    const int qloc = 32 * wq + 4 * lq;      // first of 4 query rows
    const int tloc = 64 * wt + 16 * lt;     // first of 16 targets

    const float* Qg = g_QdDup + (size_t)b * KD * 2 * HW + 2 * q0;
    const float* Pg = g_Pd + (size_t)b * KD * HW + jbase;

    const unsigned smb = (unsigned)__cvta_generic_to_shared(sm);

    float bestd[4];
    int   bestj[4];
#pragma unroll
    for (int m = 0; m < 4; m++) { bestd[m] = 3.4e38f; bestj[m] = 0; }

    auto issue = [&](int c) {
        if (c < TCHUNK) {
            int jt = c / NCHUNK, kc = c - jt * NCHUNK;
            unsigned qd = smb + (c % 3) * (SLOT_FLOATS * 4);
            unsigned pd = qd + KC * 256 * 4;
#pragma unroll
            for (int i = 0; i < 2; i++) {    // Q: 16KB (16 rows x 256 floats)
                int u = tid + i * 512, r = u >> 6, g = u & 63;
                CPA16(qd + r * 1024 + g * 16,
                      Qg + (size_t)(kc * KC + r) * (2 * HW) + g * 4);
            }
#pragma unroll
            for (int i = 0; i < 2; i++) {    // P: 16KB (16 rows x 256 floats)
                int u = tid + i * 512, r = u >> 6, g = u & 63;
                CPA16(pd + r * 1024 + g * 16,
                      Pg + (size_t)(kc * KC + r) * HW + jt * TN + g * 4);
            }
        }
        asm volatile("cp.async.commit_group;\n");
    };

    issue(0);
    issue(1);

    int c = 0;
    for (int jt = 0; jt < JTILES; jt++) {
        unsigned long long acc[4][8];
#pragma unroll
        for (int m = 0; m < 4; m++)
#pragma unroll
            for (int np = 0; np < 8; np++) acc[m][np] = 0ull;

        for (int kc = 0; kc < NCHUNK; kc++) {
            issue(c + 2);                                 // buffer (c+2)%3 free
            asm volatile("cp.async.wait_group 2;\n" ::: "memory");
            __syncthreads();

            const float* qb = sm + (c % 3) * SLOT_FLOATS + 2 * qloc;
            const float* pb = sm + (c % 3) * SLOT_FLOATS + KC * 256 + tloc;
#pragma unroll
            for (int k = 0; k < KC; k++) {
                ulonglong2 aA = *reinterpret_cast<const ulonglong2*>(qb + k * 256);
                ulonglong2 aB = *reinterpret_cast<const ulonglong2*>(qb + k * 256 + 4);
                ulonglong2 b0 = *reinterpret_cast<const ulonglong2*>(pb + k * 256);
                ulonglong2 b1 = *reinterpret_cast<const ulonglong2*>(pb + k * 256 + 4);
                ulonglong2 b2 = *reinterpret_cast<const ulonglong2*>(pb + k * 256 + 8);
                ulonglong2 b3 = *reinterpret_cast<const ulonglong2*>(pb + k * 256 + 12);
                unsigned long long ap[4] = {aA.x, aA.y, aB.x, aB.y};
                unsigned long long bp[8] = {b0.x, b0.y, b1.x, b1.y,
                                            b2.x, b2.y, b3.x, b3.y};
#pragma unroll
                for (int m = 0; m < 4; m++)
#pragma unroll
                    for (int np = 0; np < 8; np++)
                        acc[m][np] = ffma2(ap[m], bp[np], acc[m][np]);
            }
            __syncthreads();
            c++;
        }

        // Epilogue: d2 = qn - 2*cross + pn, running min (ascending j, strict <)
        int jt0 = jbase + jt * TN;
        float4 qv4 = *reinterpret_cast<const float4*>(g_qn + b * HW + q0 + qloc);
        float qnv[4] = {qv4.x, qv4.y, qv4.z, qv4.w};
        float pnv[16];
#pragma unroll
        for (int i = 0; i < 4; i++) {
            float4 p4 = *reinterpret_cast<const float4*>(
                g_pn + b * HW + jt0 + tloc + 4 * i);
            pnv[4 * i] = p4.x; pnv[4 * i + 1] = p4.y;
            pnv[4 * i + 2] = p4.z; pnv[4 * i + 3] = p4.w;
        }
#pragma unroll
        for (int m = 0; m < 4; m++) {
            float qv = qnv[m];
#pragma unroll
            for (int np = 0; np < 8; np++) {
                float fx = __uint_as_float((unsigned)(acc[m][np] & 0xffffffffull));
                float fy = __uint_as_float((unsigned)(acc[m][np] >> 32));
                float d0 = fmaf(-2.f, fx, qv) + pnv[2 * np];
                float d1 = fmaf(-2.f, fy, qv) + pnv[2 * np + 1];
                int j0 = jt0 + tloc + 2 * np;
                if (d0 < bestd[m]) { bestd[m] = d0; bestj[m] = j0; }
                if (d1 < bestd[m]) { bestd[m] = d1; bestj[m] = j0 + 1; }
            }
        }
    }

    // ---- block reduction across 16 (wt, lt) groups per query row ----
    __syncthreads();
    float* rd = sm;                         // [128][17]
    int*   rj = (int*)(sm + TM * 17);
    int grp = 4 * wt + lt;                  // ascending grp == ascending j base
#pragma unroll
    for (int m = 0; m < 4; m++) {
        rd[(qloc + m) * 17 + grp] = bestd[m];
        rj[(qloc + m) * 17 + grp] = bestj[m];
    }
    __syncthreads();

    if (tid < TM) {
        float bd = rd[tid * 17];
        int   bj = rj[tid * 17];
#pragma unroll
        for (int x = 1; x < 16; x++) {
            float d = rd[tid * 17 + x];
            int   j = rj[tid * 17 + x];
            if (d < bd || (d == bd && j < bj)) { bd = d; bj = j; }
        }
        g_part_d[(size_t)(js * NB + b) * HW + q0 + tid] = bd;
        g_part_j[(size_t)(js * NB + b) * HW + q0 + tid] = bj;
    }
}

// ---------------------------------------------------------------------------
// Merge JSPLIT partials (ascending js => ascending j; strict < keeps first)
// ---------------------------------------------------------------------------
__global__ void reduce_kernel(float* __restrict__ out) {
    int idx = blockIdx.x * blockDim.x + threadIdx.x;
    if (idx >= NB * HW) return;
    int b = idx >> 12, q = idx & (HW - 1);
    float bd = 3.4e38f; int bj = 0;
#pragma unroll
    for (int js = 0; js < JSPLIT; js++) {
        float d = g_part_d[(size_t)(js * NB + b) * HW + q];
        int   j = g_part_j[(size_t)(js * NB + b) * HW + q];
        if (d < bd) { bd = d; bj = j; }
    }
    out[(size_t)b * 2 * HW + q]               = (float)(bj >> 6);
    out[(size_t)b * 2 * HW + HW + q]          = (float)(bj & 63);
    out[(size_t)NB * 2 * HW + (size_t)b * HW + q] = bd;
}

extern "C" void kernel_launch(void* const* d_in, const int* in_sizes, int n_in,
                              void* d_out, int out_size) {
    const float* s = (const float*)d_in[0];
    const float* t = (const float*)d_in[1];
    float* out = (float*)d_out;

    cudaFuncSetAttribute(nn_kernel, cudaFuncAttributeMaxDynamicSharedMemorySize,
                         SMEM_BYTES);

    prep_kernel<<<dim3((NB * HW + 255) / 256, 2), 256>>>(s, t);
    nn_kernel<<<dim3(HW / TM, JSPLIT, NB), 512, SMEM_BYTES>>>();
    reduce_kernel<<<(NB * HW + 255) / 256, 256>>>(out);
}

// round 5
// speedup vs baseline: 1.9500x; 1.9500x over previous
#include <cuda_runtime.h>
#include <cstdint>

// Fixed problem: n=4, c=16, h=w=64, patch=3
#define NB 4
#define CH 16
#define W 64
#define HW 4096
#define JSPLIT 2
#define JSTEPS (W / JSPLIT)          // 32
#define GROW 66                      // padded G row (floats)

// smem layout (floats)
#define OFF_SS 0                     // 64 krows x 128 dup = 8192
#define OFF_ST 8192                  // ring: 4 x 16 x 64 = 4096
#define OFF_PN (8192 + 4096)         // pn: 4096
#define OFF_G  (8192 + 4096 + 4096)  // G: 2 x 64 x 66 = 8448
#define SMEM_FLOATS (OFF_G + 2 * 64 * GROW)
#define SMEM_BYTES (SMEM_FLOATS * 4) // 99328

#define CY(v) (min(max((v), 0), 63))

__device__ float g_eS[NB * HW];
__device__ float g_eT[NB * HW];
__device__ float g_qn[NB * HW];
__device__ float g_pn[NB * HW];
__device__ unsigned long long g_part[JSPLIT * NB * HW];

__device__ __forceinline__ unsigned long long ffma2(unsigned long long a,
                                                    unsigned long long b,
                                                    unsigned long long c) {
    asm("fma.rn.f32x2 %0, %1, %2, %0;" : "+l"(c) : "l"(a), "l"(b));
    return c;
}
#define CPA16(dst, src) \
    asm volatile("cp.async.cg.shared.global [%0], [%1], 16;\n" ::"r"(dst), "l"(src))

// ---------------------------------------------------------------------------
// Norms pass 1: per-pixel channel sum of squares.
// ---------------------------------------------------------------------------
__global__ void norm1_kernel(const float* __restrict__ s, const float* __restrict__ t) {
    int idx = blockIdx.x * blockDim.x + threadIdx.x;
    if (idx >= NB * HW) return;
    const float* src = blockIdx.y ? t : s;
    int b = idx >> 12, pix = idx & (HW - 1);
    float acc = 0.f;
#pragma unroll
    for (int c = 0; c < CH; c++) {
        float v = src[((size_t)(b * CH + c) << 12) + pix];
        acc = fmaf(v, v, acc);
    }
    (blockIdx.y ? g_eT : g_eS)[idx] = acc;
}

// ---------------------------------------------------------------------------
// Norms pass 2: 3x3 replicate-clamped stencil on channel sums -> qn / pn.
// ---------------------------------------------------------------------------
__global__ void norm2_kernel() {
    int idx = blockIdx.x * blockDim.x + threadIdx.x;
    if (idx >= NB * HW) return;
    const float* e = blockIdx.y ? g_eT : g_eS;
    int b = idx >> 12, pix = idx & (HW - 1);
    int iy = pix >> 6, ix = pix & 63;
    float a = 0.f;
#pragma unroll
    for (int dy = -1; dy <= 1; dy++)
#pragma unroll
        for (int dx = -1; dx <= 1; dx++)
            a += e[b * HW + CY(iy + dy) * W + CY(ix + dx)];
    (blockIdx.y ? g_pn : g_qn)[idx] = a;
}

// ---------------------------------------------------------------------------
// Fused: per (b, iy-pair, jy-half) block sweep jy. Per step:
//   G_p(ix,jx) = sum_{dy,c} s[c][CY(iy+dy)][ix] * t[c][CY(jy+dy)][jx]  (K=48)
//   cross(i,j) = sum_dx G_p(CX(ix+dx), CX(jx+dx))   (3-term diagonal stencil)
//   d2 = qn + pn - 2*cross ; argmin via packed u64 key (bits(d2)<<12 | j).
// ---------------------------------------------------------------------------
__global__ __launch_bounds__(256, 2) void nn_kernel(const float* __restrict__ s,
                                                    const float* __restrict__ t) {
    extern __shared__ float sm[];
    const int tid = threadIdx.x;
    const int blk = blockIdx.x;            // 256
    const int half = blk & 1;
    const int iyp = (blk >> 1) & 31;
    const int b = blk >> 6;
    const int iy0 = iyp * 2;
    const int jy0 = half * JSTEPS;

    const unsigned smb = (unsigned)__cvta_generic_to_shared(sm);
    const float* sB = s + ((size_t)b * CH << 12);
    const float* tB = t + ((size_t)b * CH << 12);

    // ---- prologue: build dup'd stacked S (4 rows x 16ch), pn smem ----
#pragma unroll
    for (int i = 0; i < 16; i++) {
        int idx = tid + i * 256;           // 4096 source values
        int x = idx & 63, c = (idx >> 6) & 15, e = idx >> 10;
        int row = CY(iy0 - 1 + e);
        float v = sB[(c << 12) + row * W + x];
        float2 vv; vv.x = v; vv.y = v;
        *reinterpret_cast<float2*>(sm + OFF_SS + (e * 16 + c) * 128 + 2 * x) = vv;
    }
#pragma unroll
    for (int i = 0; i < 16; i++) {
        int idx = tid + i * 256;
        sm[OFF_PN + idx] = g_pn[b * HW + idx];
    }

    // ---- ring preload: t rows CY(jy0-1), jy0, jy0+1 ----
    {
        int c = tid >> 4, x4 = tid & 15;
        int rows[3] = {CY(jy0 - 1), jy0, jy0 + 1};
#pragma unroll
        for (int r = 0; r < 3; r++) {
            int rr = rows[r];
            CPA16(smb + (OFF_ST + (rr & 3) * 1024 + c * 64 + x4 * 4) * 4,
                  tB + (c << 12) + rr * W + x4 * 4);
        }
        asm volatile("cp.async.commit_group;\n");
    }

    // GEMM mapping: warp w: p = w>>2, ix band (w&3)*16; lane: 4 ix x 8 jx
    const int w = tid >> 5, l = tid & 31;
    const int p = w >> 2;
    const int ixb = (w & 3) * 16 + (l >> 3) * 4;
    const int jxb = (l & 7) * 8;

    // epilogue mapping: (p2, ix, half-of-jx)
    const int p2 = tid >> 7;
    const int eix = (tid >> 1) & 63;
    const int ehf = tid & 1;
    const float qv = g_qn[b * HW + (iy0 + p2) * W + eix];
    const float* Gm = sm + OFF_G + p2 * 64 * GROW + CY(eix - 1) * GROW;
    const float* Gc = sm + OFF_G + p2 * 64 * GROW + eix * GROW;
    const float* Gp = sm + OFF_G + p2 * 64 * GROW + CY(eix + 1) * GROW;

    unsigned long long best = ~0ull;

    for (int jy = jy0; jy < jy0 + JSTEPS; jy++) {
        asm volatile("cp.async.wait_group 0;\n" ::: "memory");
        __syncthreads();   // ring ready; epilogue(jy-1) done before G overwrite

        // ---- GEMM: K = 48 = 3 dy x 16 c ----
        unsigned long long acc[4][4];
#pragma unroll
        for (int m = 0; m < 4; m++)
#pragma unroll
            for (int n = 0; n < 4; n++) acc[m][n] = 0ull;

#pragma unroll
        for (int dy = 0; dy < 3; dy++) {
            const float* Ar = sm + OFF_SS + (p + dy) * 16 * 128 + 2 * ixb;
            const float* Br = sm + OFF_ST + (CY(jy - 1 + dy) & 3) * 1024 + jxb;
#pragma unroll
            for (int c = 0; c < CH; c++) {
                ulonglong2 a01 = *reinterpret_cast<const ulonglong2*>(Ar + c * 128);
                ulonglong2 a23 = *reinterpret_cast<const ulonglong2*>(Ar + c * 128 + 4);
                ulonglong2 b01 = *reinterpret_cast<const ulonglong2*>(Br + c * 64);
                ulonglong2 b23 = *reinterpret_cast<const ulonglong2*>(Br + c * 64 + 4);
                unsigned long long ap[4] = {a01.x, a01.y, a23.x, a23.y};
                unsigned long long bp[4] = {b01.x, b01.y, b23.x, b23.y};
#pragma unroll
                for (int m = 0; m < 4; m++)
#pragma unroll
                    for (int n = 0; n < 4; n++)
                        acc[m][n] = ffma2(ap[m], bp[n], acc[m][n]);
            }
        }
        // store G (fp32 pairs)
#pragma unroll
        for (int m = 0; m < 4; m++)
#pragma unroll
            for (int n = 0; n < 4; n++)
                *reinterpret_cast<unsigned long long*>(
                    sm + OFF_G + p * 64 * GROW + (ixb + m) * GROW + jxb + 2 * n) =
                    acc[m][n];
        __syncthreads();

        // prefetch next t row (overwrites slot (jy+2)&3; disjoint from jy-1..jy+1)
        {
            int r2 = jy + 2;
            if (r2 <= 63 && r2 <= jy0 + JSTEPS) {
                int c = tid >> 4, x4 = tid & 15;
                CPA16(smb + (OFF_ST + (r2 & 3) * 1024 + c * 64 + x4 * 4) * 4,
                      tB + (c << 12) + r2 * W + x4 * 4);
            }
            asm volatile("cp.async.commit_group;\n");
        }

        // ---- epilogue: x-stencil + d2 + packed argmin ----
        {
            const float* pnRow = sm + OFF_PN + jy * W;
            int jbase = jy * W;
#pragma unroll 8
            for (int jj = 0; jj < 32; jj++) {
                int jx = ehf * 32 + jj;
                int jm = CY(jx - 1), jp = CY(jx + 1);
                float cross = Gm[jm] + Gc[jx] + Gp[jp];
                float d2 = fmaf(-2.f, cross, qv + pnRow[jx]);
                unsigned long long key =
                    ((unsigned long long)__float_as_uint(d2) << 12) |
                    (unsigned)(jbase + jx);
                best = key < best ? key : best;
            }
        }
        __syncthreads();   // epilogue reads of G done before next GEMM
    }

    // merge jx halves (lane pairs)
    unsigned long long o = __shfl_xor_sync(0xffffffffu, best, 1);
    best = o < best ? o : best;
    if (ehf == 0)
        g_part[(size_t)(half * NB + b) * HW + (iy0 + p2) * W + eix] = best;
}

// ---------------------------------------------------------------------------
// Merge JSPLIT halves; decode key -> (jy, jx, d2).
// ---------------------------------------------------------------------------
__global__ void reduce_kernel(float* __restrict__ out) {
    int idx = blockIdx.x * blockDim.x + threadIdx.x;
    if (idx >= NB * HW) return;
    int b = idx >> 12, q = idx & (HW - 1);
    unsigned long long best = ~0ull;
#pragma unroll
    for (int h = 0; h < JSPLIT; h++) {
        unsigned long long k = g_part[(size_t)(h * NB + b) * HW + q];
        best = k < best ? k : best;
    }
    int j = (int)(best & 4095u);
    float d2 = __uint_as_float((unsigned)(best >> 12));
    out[(size_t)b * 2 * HW + q]                    = (float)(j >> 6);
    out[(size_t)b * 2 * HW + HW + q]               = (float)(j & 63);
    out[(size_t)NB * 2 * HW + (size_t)b * HW + q]  = d2;
}

extern "C" void kernel_launch(void* const* d_in, const int* in_sizes, int n_in,
                              void* d_out, int out_size) {
    const float* s = (const float*)d_in[0];
    const float* t = (const float*)d_in[1];
    float* out = (float*)d_out;

    cudaFuncSetAttribute(nn_kernel, cudaFuncAttributeMaxDynamicSharedMemorySize,
                         SMEM_BYTES);

    norm1_kernel<<<dim3((NB * HW + 255) / 256, 2), 256>>>(s, t);
    norm2_kernel<<<dim3((NB * HW + 255) / 256, 2), 256>>>();
    nn_kernel<<<NB * 32 * JSPLIT, 256, SMEM_BYTES>>>(s, t);
    reduce_kernel<<<(NB * HW + 255) / 256, 256>>>(out);
}

// round 7
// speedup vs baseline: 2.0022x; 1.0267x over previous
#include <cuda_runtime.h>
#include <cstdint>

// Fixed problem: n=4, c=16, h=w=64, patch=3
#define NB 4
#define CH 16
#define W 64
#define HW 4096
#define JSPLIT 2
#define JSTEPS (W / JSPLIT)          // 32
#define GROW 66                      // padded G row (floats)
#define SLOT 1088                    // ring slot: 16 t rows + 1 eT row (floats)

// smem layout (floats)
#define OFF_SS 0                     // 4 A-rows x 16 c x 128 dup = 8192
#define OFF_ST 8192                  // ring: 4 x 1088 = 4352
#define OFF_G  (8192 + 4352)         // G: 2 x 64 x 66 = 8448
#define SMEM_FLOATS (OFF_G + 2 * 64 * GROW)
#define SMEM_BYTES (SMEM_FLOATS * 4) // 83968

#define CY(v) (min(max((v), 0), 63))

__device__ float g_eS[NB * HW];
__device__ float g_eT[NB * HW];
__device__ float g_qn[NB * HW];
__device__ unsigned long long g_part[JSPLIT * NB * HW];

__device__ __forceinline__ unsigned long long ffma2(unsigned long long a,
                                                    unsigned long long b,
                                                    unsigned long long c) {
    asm("fma.rn.f32x2 %0, %1, %2, %0;" : "+l"(c) : "l"(a), "l"(b));
    return c;
}
#define CPA16(dst, src) \
    asm volatile("cp.async.cg.shared.global [%0], [%1], 16;\n" ::"r"(dst), "l"(src))

// ---------------------------------------------------------------------------
// Norms pass 1: per-pixel channel sum of squares (eS and eT).
// ---------------------------------------------------------------------------
__global__ void norm1_kernel(const float* __restrict__ s, const float* __restrict__ t) {
    int idx = blockIdx.x * blockDim.x + threadIdx.x;
    if (idx >= NB * HW) return;
    const float* src = blockIdx.y ? t : s;
    int b = idx >> 12, pix = idx & (HW - 1);
    float acc = 0.f;
#pragma unroll
    for (int c = 0; c < CH; c++) {
        float v = src[((size_t)(b * CH + c) << 12) + pix];
        acc = fmaf(v, v, acc);
    }
    (blockIdx.y ? g_eT : g_eS)[idx] = acc;
}

// ---------------------------------------------------------------------------
// Norms pass 2: 3x3 replicate-clamped stencil on eS -> qn.
// ---------------------------------------------------------------------------
__global__ void norm2_kernel() {
    int idx = blockIdx.x * blockDim.x + threadIdx.x;
    if (idx >= NB * HW) return;
    int b = idx >> 12, pix = idx & (HW - 1);
    int iy = pix >> 6, ix = pix & 63;
    float a = 0.f;
#pragma unroll
    for (int dy = -1; dy <= 1; dy++)
#pragma unroll
        for (int dx = -1; dx <= 1; dx++)
            a += g_eS[b * HW + CY(iy + dy) * W + CY(ix + dx)];
    g_qn[idx] = a;
}

// ---------------------------------------------------------------------------
// Fused: per (b, iy-pair, jy-half) block sweep jy. Per step:
//   G'_p(ix,jx) = sum_dy [ sum_c (-2 s[c][iy+dy][ix]) * t[c][jy+dy][jx]
//                          + eT(jy+dy, jx) ]                        (K=51)
//   d2(ix,jx) = qn(i) + sum_dx G'_p(CX(ix+dx), CX(jx+dx))  (diag stencil)
//   argmin via packed u64 key (bits(d2)<<12 | j), min = first occurrence.
// ---------------------------------------------------------------------------
__global__ __launch_bounds__(256, 2) void nn_kernel(const float* __restrict__ s,
                                                    const float* __restrict__ t) {
    extern __shared__ float sm[];
    const int tid = threadIdx.x;
    const int blk = blockIdx.x;            // 256
    const int half = blk & 1;
    const int iyp = (blk >> 1) & 31;
    const int b = blk >> 6;
    const int iy0 = iyp * 2;
    const int jy0 = half * JSTEPS;

    const unsigned smb = (unsigned)__cvta_generic_to_shared(sm);
    const float* sB = s + ((size_t)b * CH << 12);
    const float* tB = t + ((size_t)b * CH << 12);
    const float* eT = g_eT + b * HW;

    // ---- prologue: build dup'd stacked (-2*S) (4 rows x 16 c) ----
#pragma unroll
    for (int i = 0; i < 16; i++) {
        int idx = tid + i * 256;           // 4096 source values
        int x = idx & 63, c = (idx >> 6) & 15, e = idx >> 10;
        int row = CY(iy0 - 1 + e);
        float v = -2.f * sB[(c << 12) + row * W + x];
        float2 vv; vv.x = v; vv.y = v;
        *reinterpret_cast<float2*>(sm + OFF_SS + (e * 16 + c) * 128 + 2 * x) = vv;
    }

    // ---- ring preload: rows CY(jy0-1), jy0, jy0+1 (16 t channels + eT) ----
    // 17 rows x 16 segments of 16B per ring row = 272 transfers, strided.
    {
        int rows[3] = {CY(jy0 - 1), jy0, jy0 + 1};
#pragma unroll
        for (int r = 0; r < 3; r++) {
            int rr = rows[r];
            for (int u = tid; u < 272; u += 256) {
                int c = u >> 4, seg = u & 15;
                const float* src = (c < 16) ? (tB + (c << 12) + rr * W + seg * 4)
                                            : (eT + rr * W + seg * 4);
                CPA16(smb + (OFF_ST + (rr & 3) * SLOT + c * 64 + seg * 4) * 4, src);
            }
        }
    }
    asm volatile("cp.async.commit_group;\n");

    // GEMM mapping: warp w: p = w>>2, ix band (w&3)*16; lane: 4 ix x 8 jx
    const int w = tid >> 5, l = tid & 31;
    const int p = w >> 2;
    const int ixb = (w & 3) * 16 + (l >> 3) * 4;
    const int jxb = (l & 7) * 8;

    // epilogue mapping: (p2, eix, even/odd jx)
    const int p2 = tid >> 7;
    const int eix = (tid >> 1) & 63;
    const int ehf = tid & 1;
    const float qv = g_qn[b * HW + (iy0 + p2) * W + eix];
    const float* Gm = sm + OFF_G + p2 * 64 * GROW + CY(eix - 1) * GROW;
    const float* Gc = sm + OFF_G + p2 * 64 * GROW + eix * GROW;
    const float* Gp = sm + OFF_G + p2 * 64 * GROW + CY(eix + 1) * GROW;

    const float one2[2] = {1.f, 1.f};
    const unsigned long long ONE = *reinterpret_cast<const unsigned long long*>(one2);

    unsigned long long best = ~0ull;

    for (int jy = jy0; jy < jy0 + JSTEPS; jy++) {
        asm volatile("cp.async.wait_group 0;\n" ::: "memory");
        __syncthreads();   // ring ready; epilogue(jy-1) done before G overwrite

        // ---- GEMM: K = 51 = 3 dy x (16 c + eT) ----
        unsigned long long acc[4][4];
#pragma unroll
        for (int m = 0; m < 4; m++)
#pragma unroll
            for (int n = 0; n < 4; n++) acc[m][n] = 0ull;

#pragma unroll
        for (int dy = 0; dy < 3; dy++) {
            const float* Ar = sm + OFF_SS + (p + dy) * 16 * 128 + 2 * ixb;
            const float* Br = sm + OFF_ST + (CY(jy - 1 + dy) & 3) * SLOT + jxb;
#pragma unroll
            for (int c = 0; c < CH; c++) {
                ulonglong2 a01 = *reinterpret_cast<const ulonglong2*>(Ar + c * 128);
                ulonglong2 a23 = *reinterpret_cast<const ulonglong2*>(Ar + c * 128 + 4);
                ulonglong2 b01 = *reinterpret_cast<const ulonglong2*>(Br + c * 64);
                ulonglong2 b23 = *reinterpret_cast<const ulonglong2*>(Br + c * 64 + 4);
                unsigned long long ap[4] = {a01.x, a01.y, a23.x, a23.y};
                unsigned long long bp[4] = {b01.x, b01.y, b23.x, b23.y};
#pragma unroll
                for (int m = 0; m < 4; m++)
#pragma unroll
                    for (int n = 0; n < 4; n++)
                        acc[m][n] = ffma2(ap[m], bp[n], acc[m][n]);
            }
            // eT row (A = 1): adds pn partial for this dy
            {
                ulonglong2 b01 = *reinterpret_cast<const ulonglong2*>(Br + 16 * 64);
                ulonglong2 b23 = *reinterpret_cast<const ulonglong2*>(Br + 16 * 64 + 4);
                unsigned long long bp[4] = {b01.x, b01.y, b23.x, b23.y};
#pragma unroll
                for (int m = 0; m < 4; m++)
#pragma unroll
                    for (int n = 0; n < 4; n++)
                        acc[m][n] = ffma2(ONE, bp[n], acc[m][n]);
            }
        }
        // store G' (fp32 pairs)
#pragma unroll
        for (int m = 0; m < 4; m++)
#pragma unroll
            for (int n = 0; n < 4; n++)
                *reinterpret_cast<unsigned long long*>(
                    sm + OFF_G + p * 64 * GROW + (ixb + m) * GROW + jxb + 2 * n) =
                    acc[m][n];
        __syncthreads();

        // prefetch next row (slot (jy+2)&3 disjoint from live jy-1..jy+1)
        {
            int r2 = jy + 2;
            if (r2 <= 63 && r2 <= jy0 + JSTEPS) {
                for (int u = tid; u < 272; u += 256) {
                    int c = u >> 4, seg = u & 15;
                    const float* src = (c < 16) ? (tB + (c << 12) + r2 * W + seg * 4)
                                                : (eT + r2 * W + seg * 4);
                    CPA16(smb + (OFF_ST + (r2 & 3) * SLOT + c * 64 + seg * 4) * 4, src);
                }
            }
            asm volatile("cp.async.commit_group;\n");
        }

        // ---- epilogue: diagonal stencil + packed argmin (bank-conflict-free:
        //      lanes read banks 2r+ehf, all distinct) ----
        {
            int jbase = jy * W;
#pragma unroll 8
            for (int jj = 0; jj < 32; jj++) {
                int jx = 2 * jj + ehf;
                int jm = max(jx - 1, 0), jp = min(jx + 1, 63);
                float d2 = qv + (Gm[jm] + Gc[jx] + Gp[jp]);
                unsigned long long key =
                    ((unsigned long long)__float_as_uint(d2) << 12) |
                    (unsigned)(jbase + jx);
                best = key < best ? key : best;
            }
        }
        __syncthreads();   // epilogue reads of G done before next GEMM
    }

    // merge even/odd jx lanes (adjacent lanes)
    unsigned long long o = __shfl_xor_sync(0xffffffffu, best, 1);
    best = o < best ? o : best;
    if (ehf == 0)
        g_part[(size_t)(half * NB + b) * HW + (iy0 + p2) * W + eix] = best;
}

// ---------------------------------------------------------------------------
// Merge JSPLIT halves; decode key -> (jy, jx, d2).
// ---------------------------------------------------------------------------
__global__ void reduce_kernel(float* __restrict__ out) {
    int idx = blockIdx.x * blockDim.x + threadIdx.x;
    if (idx >= NB * HW) return;
    int b = idx >> 12, q = idx & (HW - 1);
    unsigned long long best = ~0ull;
#pragma unroll
    for (int h = 0; h < JSPLIT; h++) {
        unsigned long long k = g_part[(size_t)(h * NB + b) * HW + q];
        best = k < best ? k : best;
    }
    int j = (int)(best & 4095u);
    float d2 = __uint_as_float((unsigned)(best >> 12));
    out[(size_t)b * 2 * HW + q]                    = (float)(j >> 6);
    out[(size_t)b * 2 * HW + HW + q]               = (float)(j & 63);
    out[(size_t)NB * 2 * HW + (size_t)b * HW + q]  = d2;
}

extern "C" void kernel_launch(void* const* d_in, const int* in_sizes, int n_in,
                              void* d_out, int out_size) {
    const float* s = (const float*)d_in[0];
    const float* t = (const float*)d_in[1];
    float* out = (float*)d_out;

    cudaFuncSetAttribute(nn_kernel, cudaFuncAttributeMaxDynamicSharedMemorySize,
                         SMEM_BYTES);

    norm1_kernel<<<dim3((NB * HW + 255) / 256, 2), 256>>>(s, t);
    norm2_kernel<<<(NB * HW + 255) / 256, 256>>>();
    nn_kernel<<<NB * 32 * JSPLIT, 256, SMEM_BYTES>>>(s, t);
    reduce_kernel<<<(NB * HW + 255) / 256, 256>>>(out);
}

// round 9
// speedup vs baseline: 3.7800x; 1.8880x over previous
#include <cuda_runtime.h>
#include <cstdint>

// Fixed problem: n=4, c=16, h=w=64, patch=3
#define NB 4
#define CH 16
#define W 64
#define HW 4096
#define NDIAG 127
#define RST 67            // Rbuf row stride (67 % 32 = 3 -> conflict-free cols)
#define ABST 68           // A/B buffer row stride (float2-aligned)
#define NSTG 1122         // 17 rows x 66 staged values per operand

#define CY(v) (min(max((v), 0), 63))

__device__ float g_eS[NB * HW];
__device__ float g_eT[NB * HW];
__device__ unsigned long long g_part[(size_t)NDIAG * NB * HW];

// ---------------------------------------------------------------------------
// Per-pixel channel sum of squares (eS / eT).
// ---------------------------------------------------------------------------
__global__ void norm1_kernel(const float* __restrict__ s, const float* __restrict__ t) {
    int idx = blockIdx.x * blockDim.x + threadIdx.x;
    if (idx >= NB * HW) return;
    const float* src = blockIdx.y ? t : s;
    int b = idx >> 12, pix = idx & (HW - 1);
    float acc = 0.f;
#pragma unroll
    for (int c = 0; c < CH; c++) {
        float v = src[((size_t)(b * CH + c) << 12) + pix];
        acc = fmaf(v, v, acc);
    }
    (blockIdx.y ? g_eT : g_eS)[idx] = acc;
}

// ---------------------------------------------------------------------------
// Diagonal sweep kernel. Block = (batch b, diagonal d = jy - iy).
// Sweeps padded row-pair index p: R~(p, p+d)(ix~, jx~) is a K=18 GEMM:
//   ch 0..15: (-2 s[c][CY(p-1)][CY(ix~-1)]) * t[c][CY(p+d-1)][CY(jx~-1)]
//   ch 16   : eS~(p, ix~) * 1          (query norm fold)
//   ch 17   : 1 * eT~(p+d, jx~)        (target norm fold)
// d2(iy, jy=iy+d)(ix,jx) = sum_{uy} Gx(p=iy+uy), Gx = diag-x-stencil of R~.
// Sliding window: A2 holds 2-term partial, A1 one-term. Argmin per finished
// (iy, jy) row-pair with packed key (d2bits<<12 | j) -> first occurrence.
// ---------------------------------------------------------------------------
__global__ __launch_bounds__(256, 2) void nn_kernel(const float* __restrict__ s,
                                                    const float* __restrict__ t) {
    __shared__ float Abuf[18 * ABST];
    __shared__ float Bbuf[18 * ABST];
    __shared__ float Rbuf[66 * RST];
    __shared__ unsigned long long bm[4 * 64];

    const int tid = threadIdx.x;
    const int blk = blockIdx.x;
    const int kk = blk >> 2;            // diagonal index 0..126 (|d| ascending)
    const int b = blk & 3;
    const int d = (kk == 0) ? 0 : ((kk & 1) ? ((kk + 1) >> 1) : -(kk >> 1));
    const int lo = max(0, -d);
    const int steps = 66 - abs(d);

    const float* sB = s + ((size_t)b * CH << 12);
    const float* tB = t + ((size_t)b * CH << 12);
    const float* eSb = g_eS + b * HW;
    const float* eTb = g_eT + b * HW;

    // ---- staging precompute: 5 (A,B) elements per thread ----
    const float* pA[5]; const float* pB[5];
    float wA[5]; unsigned dA[5], dB[5]; bool val[5];
    float rA[5], rB[5];
#pragma unroll
    for (int i = 0; i < 5; i++) {
        int u = tid + 256 * i;
        val[i] = (u < NSTG);
        int uu = val[i] ? u : 0;
        int m = uu / 66, xx = uu - 66 * m;
        int gx = CY(xx - 1);
        if (m < 16) { pA[i] = sB + (m << 12) + gx; wA[i] = -2.f; }
        else        { pA[i] = eSb + gx;            wA[i] = 1.f;  }
        dA[i] = m * ABST + xx;
        if (m < 16) pB[i] = tB + (m << 12) + gx;
        else        pB[i] = eTb + gx;
        dB[i] = ((m == 16) ? 17 : m) * ABST + xx;
    }
    // constant channels: A ch17 = 1, B ch16 = 1
    if (tid < 66) {
        Abuf[17 * ABST + tid] = 1.f;
        Bbuf[16 * ABST + tid] = 1.f;
    }
    // first loads (p = lo)
    {
        int ra = CY(lo - 1) * W, rb = CY(lo + d - 1) * W;
#pragma unroll
        for (int i = 0; i < 5; i++) if (val[i]) {
            rA[i] = __ldg(pA[i] + ra);
            rB[i] = __ldg(pB[i] + rb);
        }
    }

    // GEMM fragment mapping: 242 active threads, 3 ix~ x 6 jx~ each
    const bool act = tid < 242;
    const int ti = act ? (tid / 11) : 0;
    const int tj = act ? (tid - 11 * ti) : 0;

    // epilogue mapping: query ix = eix, jx band = 16*eg
    const int eix = tid & 63;
    const int eg = tid >> 6;
    const int ejx0 = eg << 4;
    const float* R0 = Rbuf + eix * RST + ejx0;
    const float* R1 = Rbuf + (eix + 1) * RST + ejx0 + 1;
    const float* R2 = Rbuf + (eix + 2) * RST + ejx0 + 2;

    float A1[16], A2[16];
#pragma unroll
    for (int jj = 0; jj < 16; jj++) { A1[jj] = 0.f; A2[jj] = 0.f; }

    for (int ss = 0; ss < steps; ss++) {
        // (1) store staged operands
#pragma unroll
        for (int i = 0; i < 5; i++) if (val[i]) {
            Abuf[dA[i]] = rA[i] * wA[i];
            Bbuf[dB[i]] = rB[i];
        }
        __syncthreads();                              // (a)

        // (2) prefetch next row pair (clamped; idle on last step)
        if (ss + 1 < steps) {
            int pn = lo + ss + 1;
            int ra = CY(pn - 1) * W, rb = CY(pn + d - 1) * W;
#pragma unroll
            for (int i = 0; i < 5; i++) if (val[i]) {
                rA[i] = __ldg(pA[i] + ra);
                rB[i] = __ldg(pB[i] + rb);
            }
        }

        // (3) K=18 GEMM -> R~ tile
        if (act) {
            float acc[3][6];
#pragma unroll
            for (int m = 0; m < 3; m++)
#pragma unroll
                for (int n = 0; n < 6; n++) acc[m][n] = 0.f;
            const float* Ap = Abuf + 3 * ti;
            const float* Bp = Bbuf + 6 * tj;
#pragma unroll 6
            for (int k = 0; k < 18; k++) {
                float a0 = Ap[k * ABST], a1 = Ap[k * ABST + 1], a2 = Ap[k * ABST + 2];
                float2 b0 = *(const float2*)(Bp + k * ABST);
                float2 b1 = *(const float2*)(Bp + k * ABST + 2);
                float2 b2 = *(const float2*)(Bp + k * ABST + 4);
                acc[0][0] = fmaf(a0, b0.x, acc[0][0]);
                acc[0][1] = fmaf(a0, b0.y, acc[0][1]);
                acc[0][2] = fmaf(a0, b1.x, acc[0][2]);
                acc[0][3] = fmaf(a0, b1.y, acc[0][3]);
                acc[0][4] = fmaf(a0, b2.x, acc[0][4]);
                acc[0][5] = fmaf(a0, b2.y, acc[0][5]);
                acc[1][0] = fmaf(a1, b0.x, acc[1][0]);
                acc[1][1] = fmaf(a1, b0.y, acc[1][1]);
                acc[1][2] = fmaf(a1, b1.x, acc[1][2]);
                acc[1][3] = fmaf(a1, b1.y, acc[1][3]);
                acc[1][4] = fmaf(a1, b2.x, acc[1][4]);
                acc[1][5] = fmaf(a1, b2.y, acc[1][5]);
                acc[2][0] = fmaf(a2, b0.x, acc[2][0]);
                acc[2][1] = fmaf(a2, b0.y, acc[2][1]);
                acc[2][2] = fmaf(a2, b1.x, acc[2][2]);
                acc[2][3] = fmaf(a2, b1.y, acc[2][3]);
                acc[2][4] = fmaf(a2, b2.x, acc[2][4]);
                acc[2][5] = fmaf(a2, b2.y, acc[2][5]);
            }
#pragma unroll
            for (int m = 0; m < 3; m++)
#pragma unroll
                for (int n = 0; n < 6; n++)
                    Rbuf[(3 * ti + m) * RST + 6 * tj + n] = acc[m][n];
        }
        __syncthreads();                              // (b)

        // (4) epilogue: Gx = diag-x-stencil; sliding window; argmin on finish
        const bool fin = (ss >= 2);
        const int jy = lo + ss - 2 + d;               // valid when fin
        unsigned long long cand = ~0ull;
        const unsigned jrow = (unsigned)(jy * W + ejx0);
#pragma unroll
        for (int jj = 0; jj < 16; jj++) {
            float g = R0[jj] + R1[jj] + R2[jj];
            if (fin) {
                float d2 = A2[jj] + g;
                unsigned long long key =
                    ((unsigned long long)__float_as_uint(d2) << 12) | (jrow + jj);
                cand = key < cand ? key : cand;
            }
            A2[jj] = A1[jj] + g;
            A1[jj] = g;
        }
        if (fin) bm[(eg << 6) + eix] = cand;
        __syncthreads();                              // (c)

        if (fin && tid < 64) {
            unsigned long long m0 = bm[tid];
            unsigned long long m1 = bm[64 + tid];
            unsigned long long m2 = bm[128 + tid];
            unsigned long long m3 = bm[192 + tid];
            m0 = m1 < m0 ? m1 : m0;
            m2 = m3 < m2 ? m3 : m2;
            m0 = m2 < m0 ? m2 : m0;
            int iy = lo + ss - 2;
            g_part[((size_t)kk * NB + b) * HW + iy * W + tid] = m0;
        }
    }
}

// ---------------------------------------------------------------------------
// Merge 64 diagonal partials per query; decode key.
// ---------------------------------------------------------------------------
__global__ void reduce_kernel(float* __restrict__ out) {
    int idx = blockIdx.x * blockDim.x + threadIdx.x;
    if (idx >= NB * HW) return;
    int b = idx >> 12, q = idx & (HW - 1);
    int iy = q >> 6;
    unsigned long long best = ~0ull;
    for (int jy = 0; jy < W; jy++) {
        int dd = jy - iy;
        int kk = (dd == 0) ? 0 : ((dd > 0) ? 2 * dd - 1 : -2 * dd);
        unsigned long long k = g_part[((size_t)kk * NB + b) * HW + q];
        best = k < best ? k : best;
    }
    int j = (int)(best & 4095u);
    float d2 = __uint_as_float((unsigned)(best >> 12));
    out[(size_t)b * 2 * HW + q]                    = (float)(j >> 6);
    out[(size_t)b * 2 * HW + HW + q]               = (float)(j & 63);
    out[(size_t)NB * 2 * HW + (size_t)b * HW + q]  = d2;
}

extern "C" void kernel_launch(void* const* d_in, const int* in_sizes, int n_in,
                              void* d_out, int out_size) {
    const float* s = (const float*)d_in[0];
    const float* t = (const float*)d_in[1];
    float* out = (float*)d_out;

    norm1_kernel<<<dim3((NB * HW + 255) / 256, 2), 256>>>(s, t);
    nn_kernel<<<NDIAG * NB, 256>>>(s, t);
    reduce_kernel<<<(NB * HW + 255) / 256, 256>>>(out);
}